// round 2
// baseline (speedup 1.0000x reference)
#include <cuda_runtime.h>
#include <cstdint>

// Problem shape (from reference setup_inputs): B=64, S=1024, D=512, T=2048.
// S, D, T are re-derived from in_sizes/out_size at launch; B is fixed.
#define BATCH 64
#define MAX_S 1024

// Scratch (no allocations allowed): per-batch inclusive cumsum + total lengths.
__device__ int g_cum[BATCH * MAX_S];
__device__ int g_len[BATCH];

// ---------------------------------------------------------------------------
// Kernel 1: per-batch inclusive scan of durations. One block per batch,
// S threads, Hillis-Steele in shared memory (log2(S)=10 steps).
// ---------------------------------------------------------------------------
__global__ void cumsum_kernel(const int* __restrict__ dur, int S) {
    __shared__ int sh[MAX_S];
    const int tid = threadIdx.x;
    const int b   = blockIdx.x;

    sh[tid] = dur[b * S + tid];
    __syncthreads();

    #pragma unroll
    for (int off = 1; off < MAX_S; off <<= 1) {
        int add = (tid >= off) ? sh[tid - off] : 0;
        __syncthreads();
        sh[tid] += add;
        __syncthreads();
    }

    g_cum[b * S + tid] = sh[tid];
    if (tid == S - 1) g_len[b] = sh[tid];
}

// ---------------------------------------------------------------------------
// Kernel 2: gather. One 128-thread group per output row (b, t); two groups
// per 256-thread block. Each group:
//   - binary-searches cum[b, :] for idx = searchsorted(cum, t, 'right')
//     (all threads redundantly; identical addresses -> L1 broadcast)
//   - copies x[b, idx, :] (D=512 floats) as one float4 per thread,
//     or zeros if t >= length[b]
//   - lane 0 writes mask[b, t] (1.0 if t >= length else 0.0)
// ---------------------------------------------------------------------------
__global__ void gather_kernel(const float* __restrict__ x,
                              float* __restrict__ out,
                              float* __restrict__ mask,
                              int S, int T, int D) {
    const int row  = blockIdx.x * 2 + (threadIdx.x >> 7);   // global (b,t) row
    const int lane = threadIdx.x & 127;
    const int b = row / T;
    const int t = row - b * T;

    const int* __restrict__ cum = g_cum + b * S;
    const int  len    = g_len[b];
    const bool masked = (t >= len);

    if (lane == 0) mask[row] = masked ? 1.0f : 0.0f;

    const size_t out_base = (size_t)row * D;

    if (masked) {
        const float4 z = make_float4(0.f, 0.f, 0.f, 0.f);
        for (int c = lane * 4; c < D; c += 512)
            *reinterpret_cast<float4*>(out + out_base + c) = z;
        return;
    }

    // searchsorted(cum, t, side='right'): count of cum[j] <= t
    int lo = 0, hi = S;
    while (lo < hi) {
        int mid = (lo + hi) >> 1;
        if (__ldg(cum + mid) <= t) lo = mid + 1; else hi = mid;
    }
    const int idx = min(lo, S - 1);

    const size_t src_base = ((size_t)b * S + idx) * D;
    for (int c = lane * 4; c < D; c += 512) {
        float4 v = *reinterpret_cast<const float4*>(x + src_base + c);
        *reinterpret_cast<float4*>(out + out_base + c) = v;
    }
}

// ---------------------------------------------------------------------------
extern "C" void kernel_launch(void* const* d_in, const int* in_sizes, int n_in,
                              void* d_out, int out_size) {
    const float* x   = (const float*)d_in[0];
    const int*   dur = (const int*)d_in[1];

    const int BS = in_sizes[1];          // B*S = 65536
    const int B  = BATCH;                // 64
    const int S  = BS / B;               // 1024
    const int D  = in_sizes[0] / BS;     // 512
    const int T  = out_size / (B * (D + 1));  // out_size = B*T*D + B*T -> 2048

    float* out  = (float*)d_out;
    float* mask = out + (size_t)B * T * D;

    cumsum_kernel<<<B, S>>>(dur, S);
    // one 128-thread group per output row, 2 groups per block
    gather_kernel<<<(B * T) / 2, 256>>>(x, out, mask, S, T, D);
}

// round 3
// speedup vs baseline: 1.9646x; 1.9646x over previous
#include <cuda_runtime.h>
#include <cstdint>

// Shape (from reference setup_inputs): B=64, S=1024, D=512, T=2048.
// S, D, T re-derived from in_sizes/out_size at launch; B fixed.
#define BATCH 64
#define MAX_S 1024
#define MAX_T 4096

// Scratch (no allocations allowed).
__device__ int g_idx[BATCH * MAX_T];   // idx[b][t] = source row for output slot t
__device__ int g_len[BATCH];           // total length per batch

// ---------------------------------------------------------------------------
// Kernel 1 (fused prep): per-batch inclusive scan of durations, then scatter
// the inverse map: source s owns output slots [cum[s]-dur[s], cum[s]).
// One block per batch, S threads.
// ---------------------------------------------------------------------------
__global__ void prep_kernel(const int* __restrict__ dur, int S, int T) {
    __shared__ int sh[MAX_S];
    const int tid = threadIdx.x;
    const int b   = blockIdx.x;

    const int d = dur[b * S + tid];
    sh[tid] = d;
    __syncthreads();

    #pragma unroll
    for (int off = 1; off < MAX_S; off <<= 1) {
        int add = (tid >= off) ? sh[tid - off] : 0;
        __syncthreads();
        sh[tid] += add;
        __syncthreads();
    }

    const int end   = sh[tid];          // cum[tid] (inclusive)
    const int start = end - d;
    const int len   = sh[S - 1];

    if (tid == 0) g_len[b] = len;

    // Scatter: slots [start, min(end, T)) get source index tid.
    int* __restrict__ idx = g_idx + b * T;
    const int stop = min(end, T);
    for (int p = start; p < stop; ++p) idx[p] = tid;
    // Slots in [len, T) are masked (zeroed) by the gather kernel; their idx
    // is never read, matching the reference where idx is clamped but unused.
}

// ---------------------------------------------------------------------------
// Kernel 2: gather/copy. One 128-thread group per output row (b, t);
// two groups per 256-thread block. No search: idx[row] is one broadcast load.
// Output stores are streaming (__stcs) — 256 MB with zero reuse; keep L2 for
// the duplicated source-row reads.
// ---------------------------------------------------------------------------
__global__ void gather_kernel(const float* __restrict__ x,
                              float* __restrict__ out,
                              float* __restrict__ mask,
                              int S, int T, int D) {
    const int row  = blockIdx.x * 2 + (threadIdx.x >> 7);   // global (b,t) row
    const int lane = threadIdx.x & 127;
    const int b = row / T;
    const int t = row - b * T;

    const int  len    = g_len[b];
    const bool masked = (t >= len);

    if (lane == 0) mask[row] = masked ? 1.0f : 0.0f;

    float4* __restrict__ dst =
        reinterpret_cast<float4*>(out + (size_t)row * D) + lane;

    if (masked) {
        __stcs(dst, make_float4(0.f, 0.f, 0.f, 0.f));
        return;
    }

    const int idx = __ldg(g_idx + row);   // broadcast: same addr for whole group
    const float4 v = *(reinterpret_cast<const float4*>(
                           x + ((size_t)b * S + idx) * D) + lane);
    __stcs(dst, v);
}

// ---------------------------------------------------------------------------
extern "C" void kernel_launch(void* const* d_in, const int* in_sizes, int n_in,
                              void* d_out, int out_size) {
    const float* x   = (const float*)d_in[0];
    const int*   dur = (const int*)d_in[1];

    const int BS = in_sizes[1];               // B*S = 65536
    const int B  = BATCH;                     // 64
    const int S  = BS / B;                    // 1024
    const int D  = in_sizes[0] / BS;          // 512
    const int T  = out_size / (B * (D + 1));  // 2048

    float* out  = (float*)d_out;
    float* mask = out + (size_t)B * T * D;

    prep_kernel<<<B, S>>>(dur, S, T);
    gather_kernel<<<(B * T) / 2, 256>>>(x, out, mask, S, T, D);
}

// round 7
// speedup vs baseline: 3.6072x; 1.8361x over previous
#include <cuda_runtime.h>
#include <cstdint>

// Shape (from reference setup_inputs): B=64, S=1024, D=512, T=2048.
// S, D, T re-derived from in_sizes/out_size at launch; B fixed.
#define BATCH 64
#define MAX_S 1024
#define MAX_T 4096
#define ROWS  8        // output rows per 128-thread group (T must be divisible)

// Scratch (no allocations allowed).
__device__ int g_idx[BATCH * MAX_T];   // idx[b][t] = source row for output slot t
__device__ int g_len[BATCH];           // total length per batch

// ---------------------------------------------------------------------------
// Kernel 1 (fused prep): per-batch inclusive scan of durations, then scatter
// the inverse map: source s owns output slots [cum[s]-dur[s], cum[s]).
// One block per batch, S threads.
// ---------------------------------------------------------------------------
__global__ void prep_kernel(const int* __restrict__ dur, int S, int T) {
    __shared__ int sh[MAX_S];
    const int tid = threadIdx.x;
    const int b   = blockIdx.x;

    const int d = dur[b * S + tid];
    sh[tid] = d;
    __syncthreads();

    #pragma unroll
    for (int off = 1; off < MAX_S; off <<= 1) {
        int add = (tid >= off) ? sh[tid - off] : 0;
        __syncthreads();
        sh[tid] += add;
        __syncthreads();
    }

    const int end   = sh[tid];          // inclusive cumsum
    const int start = end - d;
    const int len   = sh[S - 1];

    if (tid == 0) g_len[b] = len;

    int* __restrict__ idx = g_idx + b * T;
    const int stop = min(end, T);
    for (int p = start; p < stop; ++p) idx[p] = tid;
    // Slots in [len, T) are masked (zeroed) by the gather kernel; their idx
    // is never read.
}

// ---------------------------------------------------------------------------
// Kernel 2: gather/copy. One 128-thread group per ROWS consecutive output
// rows (same batch); two groups per 256-thread block. Each thread keeps one
// float4 column slot and issues ROWS independent loads (MLP=ROWS), then ROWS
// streaming stores. idx loads are same-address broadcasts (L1 hit).
// ---------------------------------------------------------------------------
__global__ void gather_kernel(const float* __restrict__ x,
                              float* __restrict__ out,
                              float* __restrict__ mask,
                              int S, int T, int D) {
    const int group = blockIdx.x * 2 + (threadIdx.x >> 7);
    const int lane  = threadIdx.x & 127;
    const int row0  = group * ROWS;            // first (b,t) row of this group
    const int b     = row0 / T;                // ROWS divides T -> same batch
    const int t0    = row0 - b * T;

    const int len = g_len[b];

    // mask: ROWS elements, one per leading lane
    if (lane < ROWS)
        mask[row0 + lane] = (t0 + lane >= len) ? 1.0f : 0.0f;

    // source indices (broadcast loads, unrolled -> front-batched)
    int idx[ROWS];
    #pragma unroll
    for (int r = 0; r < ROWS; ++r)
        idx[r] = __ldg(g_idx + row0 + r);

    const float4* __restrict__ xv =
        reinterpret_cast<const float4*>(x + (size_t)b * S * D) + lane;
    const int strideV = D >> 2;                // float4s per row (=128)

    // ROWS independent loads in flight
    float4 v[ROWS];
    #pragma unroll
    for (int r = 0; r < ROWS; ++r) {
        if (t0 + r < len)
            v[r] = xv[(size_t)idx[r] * strideV];
        else
            v[r] = make_float4(0.f, 0.f, 0.f, 0.f);
    }

    float4* __restrict__ dst =
        reinterpret_cast<float4*>(out + (size_t)row0 * D) + lane;
    #pragma unroll
    for (int r = 0; r < ROWS; ++r)
        __stcs(dst + (size_t)r * strideV, v[r]);
}

// ---------------------------------------------------------------------------
extern "C" void kernel_launch(void* const* d_in, const int* in_sizes, int n_in,
                              void* d_out, int out_size) {
    const float* x   = (const float*)d_in[0];
    const int*   dur = (const int*)d_in[1];

    const int BS = in_sizes[1];               // B*S = 65536
    const int B  = BATCH;                     // 64
    const int S  = BS / B;                    // 1024
    const int D  = in_sizes[0] / BS;          // 512
    const int T  = out_size / (B * (D + 1));  // 2048

    float* out  = (float*)d_out;
    float* mask = out + (size_t)B * T * D;

    prep_kernel<<<B, S>>>(dur, S, T);
    // (B*T/ROWS) groups, 2 groups per 256-thread block
    gather_kernel<<<(B * T / ROWS) / 2, 256>>>(x, out, mask, S, T, D);
}

// round 8
// speedup vs baseline: 3.6111x; 1.0011x over previous
#include <cuda_runtime.h>
#include <cstdint>

// Shape (from reference setup_inputs): B=64, S=1024, D=512, T=2048.
// S, D, T re-derived from in_sizes/out_size at launch; B fixed.
#define BATCH 64
#define MAX_S 1024
#define MAX_T 4096
#define ROWS  8        // output rows per 128-thread group (T must be divisible)

// Scratch (no allocations allowed).
__device__ int g_idx[BATCH * MAX_T];   // idx[b][t] = source row for output slot t
__device__ int g_len[BATCH];           // total length per batch

// ---------------------------------------------------------------------------
// Kernel 1 (fused prep): per-batch inclusive scan via warp shuffles
// (2 barriers instead of 20), then scatter the inverse map
// (source s owns output slots [cum[s]-dur[s], cum[s])) and write the mask.
// One block per batch, S=1024 threads.
// ---------------------------------------------------------------------------
__global__ void prep_kernel(const int* __restrict__ dur,
                            float* __restrict__ mask, int S, int T) {
    __shared__ int warp_sums[32];
    __shared__ int s_len;
    const int tid = threadIdx.x;
    const int b   = blockIdx.x;
    const int ln  = tid & 31;

    const int d = dur[b * S + tid];

    // intra-warp inclusive scan
    int v = d;
    #pragma unroll
    for (int o = 1; o < 32; o <<= 1) {
        int n = __shfl_up_sync(0xffffffffu, v, o);
        if (ln >= o) v += n;
    }
    if (ln == 31) warp_sums[tid >> 5] = v;
    __syncthreads();

    // scan of the 32 warp totals by warp 0
    if (tid < 32) {
        int w = warp_sums[tid];
        #pragma unroll
        for (int o = 1; o < 32; o <<= 1) {
            int n = __shfl_up_sync(0xffffffffu, w, o);
            if (tid >= o) w += n;
        }
        warp_sums[tid] = w;
        if (tid == 31) s_len = w;
    }
    __syncthreads();

    const int base  = (tid >= 32) ? warp_sums[(tid >> 5) - 1] : 0;
    const int end   = base + v;          // inclusive cumsum
    const int start = end - d;
    const int len   = s_len;

    if (tid == 0) g_len[b] = len;

    // mask for this batch (coalesced; T/S = 2 iterations)
    for (int p = tid; p < T; p += S)
        mask[b * T + p] = (p >= len) ? 1.0f : 0.0f;

    // inverse-map scatter: slots [start, min(end, T)) get source index tid
    int* __restrict__ idx = g_idx + b * T;
    const int stop = min(end, T);
    for (int p = start; p < stop; ++p) idx[p] = tid;
    // Slots in [len, T) are never read (gather zero-fills them).
}

// ---------------------------------------------------------------------------
// Kernel 2: gather/copy. One 128-thread group per ROWS consecutive output
// rows (same batch); two groups per 256-thread block. Each thread keeps one
// float4 column slot and issues ROWS independent loads (MLP=ROWS), then ROWS
// streaming stores. idx loads: two int4 broadcasts.
// ---------------------------------------------------------------------------
__global__ void gather_kernel(const float* __restrict__ x,
                              float* __restrict__ out,
                              int S, int T, int D) {
    const int group = blockIdx.x * 2 + (threadIdx.x >> 7);
    const int lane  = threadIdx.x & 127;
    const int row0  = group * ROWS;            // first (b,t) row of this group
    const int b     = row0 / T;                // ROWS divides T -> same batch
    const int t0    = row0 - b * T;

    const int len = g_len[b];

    // source indices: 32B broadcast (values for masked slots unused; any
    // stale value there is a previously-written index in [0, S), in-bounds)
    const int4* __restrict__ ip =
        reinterpret_cast<const int4*>(g_idx + row0);
    const int4 i0 = __ldg(ip);
    const int4 i1 = __ldg(ip + 1);
    const int idx[ROWS] = {i0.x, i0.y, i0.z, i0.w, i1.x, i1.y, i1.z, i1.w};

    const float4* __restrict__ xv =
        reinterpret_cast<const float4*>(x + (size_t)b * S * D) + lane;
    const int strideV = D >> 2;                // float4s per row (=128)

    // ROWS independent loads in flight
    float4 v[ROWS];
    #pragma unroll
    for (int r = 0; r < ROWS; ++r) {
        if (t0 + r < len)
            v[r] = xv[(size_t)idx[r] * strideV];
        else
            v[r] = make_float4(0.f, 0.f, 0.f, 0.f);
    }

    float4* __restrict__ dst =
        reinterpret_cast<float4*>(out + (size_t)row0 * D) + lane;
    #pragma unroll
    for (int r = 0; r < ROWS; ++r)
        __stcs(dst + (size_t)r * strideV, v[r]);
}

// ---------------------------------------------------------------------------
extern "C" void kernel_launch(void* const* d_in, const int* in_sizes, int n_in,
                              void* d_out, int out_size) {
    const float* x   = (const float*)d_in[0];
    const int*   dur = (const int*)d_in[1];

    const int BS = in_sizes[1];               // B*S = 65536
    const int B  = BATCH;                     // 64
    const int S  = BS / B;                    // 1024
    const int D  = in_sizes[0] / BS;          // 512
    const int T  = out_size / (B * (D + 1));  // 2048

    float* out  = (float*)d_out;
    float* mask = out + (size_t)B * T * D;

    prep_kernel<<<B, S>>>(dur, mask, S, T);
    gather_kernel<<<(B * T / ROWS) / 2, 256>>>(x, out, S, T, D);
}